// round 2
// baseline (speedup 1.0000x reference)
#include <cuda_runtime.h>

#define NT 256
#define L_IN 4096
#define DZV 30
#define CV 10
#define NPG 15
#define B_TOT 512

typedef unsigned long long u64;

// ---------------- packed constants ----------------
// cW1p: [d][(ch*3+k)][ocpair]   pairs over oc (4 oc -> 2 pairs)
// cW2p: [d][(ch*3+k)][ocpair]   (8 oc -> 4 pairs)
// cW3p: [d][half][(ch*3+k)][ocpair] (half = oc/4, 2 pairs per half)
__constant__ u64  cW1p[DZV*48];
__constant__ u64  cW2p[DZV*48];
__constant__ u64  cW3p[DZV*96];
__constant__ u64  cB1[DZV*2];    // bias pairs (oc adjacent already)
__constant__ u64  cB2[DZV*4];
__constant__ u64  cB3[DZV*4];
__constant__ float cWh[DZV*80];  // [d][c][j]
__constant__ float cZ[DZV];

__device__ float g_wscratch[DZV*384];

// ---------------- f32x2 helpers ----------------
__device__ __forceinline__ u64 dup2(float v) {
    u64 r; asm("mov.b64 %0, {%1, %1};" : "=l"(r) : "f"(v)); return r;
}
__device__ __forceinline__ void unpack2(u64 v, float& lo, float& hi) {
    asm("mov.b64 {%0, %1}, %2;" : "=f"(lo), "=f"(hi) : "l"(v));
}
__device__ __forceinline__ u64 ffma2(u64 a, u64 b, u64 c) {
    u64 d; asm("fma.rn.f32x2 %0, %1, %2, %3;" : "=l"(d) : "l"(a), "l"(b), "l"(c)); return d;
}

// ---------------- repack weights into pair-friendly layout ----------------
__global__ void repack_kernel(const float* __restrict__ W1,
                              const float* __restrict__ W2,
                              const float* __restrict__ W3) {
    int i = blockIdx.x * blockDim.x + threadIdx.x;
    if (i < DZV*96) {   // W1: src [d][oc<4][ch<8][k<3] -> dst [d][(ch*3+k)][oc]
        int d = i / 96, r = i % 96;
        int oc = r & 3, ch3k = r >> 2, ch = ch3k / 3, k = ch3k % 3;
        g_wscratch[i] = W1[d*96 + oc*24 + ch*3 + k];
    }
    if (i < DZV*96) {   // W2: src [d][oc<8][ch<4][k<3] -> dst [d][(ch*3+k)][oc]
        int d = i / 96, r = i % 96;
        int oc = r & 7, ch3k = r >> 3, ch = ch3k / 3, k = ch3k % 3;
        g_wscratch[2880 + i] = W2[d*96 + oc*12 + ch*3 + k];
    }
    if (i < DZV*192) {  // W3: src [d][oc<8][ch<8][k<3] -> dst [d][half][(ch*3+k)][oc4]
        int d = i / 192, r = i % 192;
        int half = r / 96, rr = r % 96;
        int oc4 = rr & 3, ch3k = rr >> 2, ch = ch3k / 3, k = ch3k % 3;
        g_wscratch[5760 + i] = W3[d*192 + (half*4 + oc4)*24 + ch*3 + k];
    }
}

// ---------------- out init: out[b,c] = sum_d z[d]*bh[d,c] ----------------
__global__ void init_out_kernel(const float* __restrict__ z,
                                const float* __restrict__ bh,
                                float* __restrict__ out) {
    int i = blockIdx.x * blockDim.x + threadIdx.x;
    if (i < B_TOT*CV) {
        int c = i % CV;
        float s = 0.f;
        #pragma unroll
        for (int d = 0; d < DZV; d++) s = fmaf(z[d], bh[d*CV + c], s);
        out[i] = s;
    }
}

// ---------------- smem layout (chunked) ----------------
#define XS_STR 2064
#define H1_STR 1032
#define H2_STR 520
#define H1_OFF (8*XS_STR)                 // 16512
#define H2_OFF (H1_OFF + 4*H1_STR)        // 20640
#define RED_OFF (H2_OFF + 8*H2_STR)       // 24800
#define SMEM_FLOATS (RED_OFF + 64)        // 24864 -> 99456 B

__global__ __launch_bounds__(NT, 2)
void ensemble_kernel(const int* __restrict__ ids,
                     const float* __restrict__ mask,
                     const float* __restrict__ embed,
                     float* __restrict__ out)
{
    extern __shared__ float sm[];
    float* xs  = sm;
    float* h1  = sm + H1_OFF;
    float* h2  = sm + H2_OFF;
    float* red = sm + RED_OFF;

    const int tid  = threadIdx.x;
    const int lane = tid & 31;
    const int warp = tid >> 5;
    const int b    = blockIdx.x;
    const int c    = blockIdx.y;   // sequence chunk 0/1
    const int g    = blockIdx.z;   // net group 0/1

    // chunk ranges (conv3 out p, conv2 out q, conv1 out r, input x)
    const int p_lo = 511 * c;
    const int p_cnt = c ? 510 : 511;
    const int q_lo = p_lo;
    const int q_cnt = c ? 512 : 513;
    const int r_lo = 2 * q_lo;
    const int r_cnt = c ? 1025 : 1027;
    const int x_lo = 2 * r_lo;
    const int x_cnt = 2 * r_cnt + 1;       // 2055 / 2051

    // ---- gather masked embeddings for this chunk, channel-major ----
    #pragma unroll 1
    for (int i = tid; i < x_cnt; i += NT) {
        int gi = x_lo + i;
        int   id = __ldg(&ids[b*L_IN + gi]);
        float m  = __ldg(&mask[b*L_IN + gi]);
        float4 e0 = __ldg((const float4*)(embed + (size_t)id*8));
        float4 e1 = __ldg((const float4*)(embed + (size_t)id*8 + 4));
        xs[0*XS_STR+i] = e0.x*m; xs[1*XS_STR+i] = e0.y*m;
        xs[2*XS_STR+i] = e0.z*m; xs[3*XS_STR+i] = e0.w*m;
        xs[4*XS_STR+i] = e1.x*m; xs[5*XS_STR+i] = e1.y*m;
        xs[6*XS_STR+i] = e1.z*m; xs[7*XS_STR+i] = e1.w*m;
    }
    __syncthreads();

    float oacc = 0.f;   // warp0, lane<10: accumulated output class contribution

    #pragma unroll 1
    for (int dn = 0; dn < NPG; dn++) {
        const int d = g*NPG + dn;

        // ======== conv1: xs -> h1 (K3 S2, 8->4, ReLU), 4 pos/thread ========
        {
            const u64* cw = cW1p + d*48;
            const u64 b0 = cB1[d*2+0], b1 = cB1[d*2+1];
            #pragma unroll 1
            for (int it = 0; it < 2; it++) {
                const int r0 = (it*NT + tid) * 4;
                if (r0 < r_cnt) {
                    u64 acc[4][2];
                    #pragma unroll
                    for (int p = 0; p < 4; p++) { acc[p][0] = b0; acc[p][1] = b1; }
                    #pragma unroll
                    for (int ch = 0; ch < 8; ch++) {
                        const float* row = xs + ch*XS_STR + 2*r0;
                        float4 v0 = *(const float4*)row;
                        float4 v1 = *(const float4*)(row + 4);
                        float  v8 = row[8];
                        float wv[9] = {v0.x,v0.y,v0.z,v0.w,v1.x,v1.y,v1.z,v1.w,v8};
                        u64 xx[9];
                        #pragma unroll
                        for (int i = 0; i < 9; i++) xx[i] = dup2(wv[i]);
                        #pragma unroll
                        for (int p = 0; p < 4; p++) {
                            #pragma unroll
                            for (int k = 0; k < 3; k++) {
                                u64 x2 = xx[2*p + k];
                                acc[p][0] = ffma2(cw[(ch*3+k)*2+0], x2, acc[p][0]);
                                acc[p][1] = ffma2(cw[(ch*3+k)*2+1], x2, acc[p][1]);
                            }
                        }
                    }
                    float o[4][4];
                    #pragma unroll
                    for (int p = 0; p < 4; p++) {
                        float a0,a1,a2,a3;
                        unpack2(acc[p][0], a0, a1);
                        unpack2(acc[p][1], a2, a3);
                        o[p][0]=fmaxf(a0,0.f); o[p][1]=fmaxf(a1,0.f);
                        o[p][2]=fmaxf(a2,0.f); o[p][3]=fmaxf(a3,0.f);
                    }
                    if (r0 + 3 < r_cnt) {
                        #pragma unroll
                        for (int oc = 0; oc < 4; oc++)
                            *(float4*)(h1 + oc*H1_STR + r0) =
                                make_float4(o[0][oc], o[1][oc], o[2][oc], o[3][oc]);
                    } else {
                        #pragma unroll
                        for (int p = 0; p < 4; p++)
                            if (r0 + p < r_cnt)
                                #pragma unroll
                                for (int oc = 0; oc < 4; oc++)
                                    h1[oc*H1_STR + r0 + p] = o[p][oc];
                    }
                }
            }
        }
        __syncthreads();

        // ======== conv2: h1 -> h2 (K3 S2, 4->8, ReLU), 2 pos/thread ========
        {
            const u64* cw = cW2p + d*48;
            u64 bb[4];
            #pragma unroll
            for (int i = 0; i < 4; i++) bb[i] = cB2[d*4+i];
            #pragma unroll 1
            for (int it = 0; it < 2; it++) {
                const int q0 = (it*NT + tid) * 2;
                if (q0 < q_cnt) {
                    u64 acc[2][4];
                    #pragma unroll
                    for (int p = 0; p < 2; p++)
                        #pragma unroll
                        for (int pr = 0; pr < 4; pr++) acc[p][pr] = bb[pr];
                    #pragma unroll
                    for (int ch = 0; ch < 4; ch++) {
                        const float* row = h1 + ch*H1_STR + 2*q0;
                        float4 v0 = *(const float4*)row;
                        float  v4 = row[4];
                        float wv[5] = {v0.x,v0.y,v0.z,v0.w,v4};
                        u64 xx[5];
                        #pragma unroll
                        for (int i = 0; i < 5; i++) xx[i] = dup2(wv[i]);
                        #pragma unroll
                        for (int p = 0; p < 2; p++) {
                            #pragma unroll
                            for (int k = 0; k < 3; k++) {
                                u64 x2 = xx[2*p + k];
                                #pragma unroll
                                for (int pr = 0; pr < 4; pr++)
                                    acc[p][pr] = ffma2(cw[(ch*3+k)*4+pr], x2, acc[p][pr]);
                            }
                        }
                    }
                    float o[2][8];
                    #pragma unroll
                    for (int p = 0; p < 2; p++)
                        #pragma unroll
                        for (int pr = 0; pr < 4; pr++) {
                            float lo, hi;
                            unpack2(acc[p][pr], lo, hi);
                            o[p][2*pr+0] = fmaxf(lo, 0.f);
                            o[p][2*pr+1] = fmaxf(hi, 0.f);
                        }
                    if (q0 + 1 < q_cnt) {
                        #pragma unroll
                        for (int oc = 0; oc < 8; oc++)
                            *(float2*)(h2 + oc*H2_STR + q0) = make_float2(o[0][oc], o[1][oc]);
                    } else {
                        #pragma unroll
                        for (int oc = 0; oc < 8; oc++)
                            h2[oc*H2_STR + q0] = o[0][oc];
                    }
                }
            }
        }
        __syncthreads();

        // ======== conv3 + ReLU + pool partial: h2 -> psum[8], 2 pos/thread ========
        float psum[8];
        #pragma unroll
        for (int i = 0; i < 8; i++) psum[i] = 0.f;
        {
            const int p0 = tid * 2;
            if (p0 < p_cnt) {
                #pragma unroll
                for (int half = 0; half < 2; half++) {
                    const u64* cw = cW3p + d*96 + half*48;
                    const u64 b0 = cB3[d*4 + half*2 + 0];
                    const u64 b1 = cB3[d*4 + half*2 + 1];
                    u64 acc[2][2];
                    acc[0][0]=b0; acc[0][1]=b1; acc[1][0]=b0; acc[1][1]=b1;
                    #pragma unroll
                    for (int ch = 0; ch < 8; ch++) {
                        const float* row = h2 + ch*H2_STR + p0;
                        float2 a0 = *(const float2*)row;
                        float2 a1 = *(const float2*)(row + 2);
                        float wv[4] = {a0.x, a0.y, a1.x, a1.y};
                        u64 xx[4];
                        #pragma unroll
                        for (int i = 0; i < 4; i++) xx[i] = dup2(wv[i]);
                        #pragma unroll
                        for (int p = 0; p < 2; p++) {
                            #pragma unroll
                            for (int k = 0; k < 3; k++) {
                                u64 x2 = xx[p + k];
                                acc[p][0] = ffma2(cw[(ch*3+k)*2+0], x2, acc[p][0]);
                                acc[p][1] = ffma2(cw[(ch*3+k)*2+1], x2, acc[p][1]);
                            }
                        }
                    }
                    #pragma unroll
                    for (int p = 0; p < 2; p++) {
                        if (p0 + p < p_cnt) {
                            float a0,a1,a2,a3;
                            unpack2(acc[p][0], a0, a1);
                            unpack2(acc[p][1], a2, a3);
                            psum[half*4+0] += fmaxf(a0, 0.f);
                            psum[half*4+1] += fmaxf(a1, 0.f);
                            psum[half*4+2] += fmaxf(a2, 0.f);
                            psum[half*4+3] += fmaxf(a3, 0.f);
                        }
                    }
                }
            }
        }

        // ---- warp reduce psum -> red[warp][oc] ----
        #pragma unroll
        for (int oc = 0; oc < 8; oc++) {
            float s = psum[oc];
            #pragma unroll
            for (int off = 16; off > 0; off >>= 1)
                s += __shfl_down_sync(0xFFFFFFFFu, s, off);
            if (lane == 0) red[warp*8 + oc] = s;
        }
        __syncthreads();

        // ---- warp0: cross-warp reduce + head matvec ----
        if (warp == 0) {
            float s = red[lane] + red[lane + 32];
            s += __shfl_xor_sync(0xFFFFFFFFu, s, 8);
            s += __shfl_xor_sync(0xFFFFFFFFu, s, 16);
            // lanes 0..7 (and replicas) hold pooled-sum[oc]
            float pj[8];
            #pragma unroll
            for (int j = 0; j < 8; j++)
                pj[j] = __shfl_sync(0xFFFFFFFFu, s, j);
            if (lane < CV) {
                float v = 0.f;
                #pragma unroll
                for (int j = 0; j < 8; j++)
                    v = fmaf(pj[j], cWh[(d*CV + lane)*8 + j], v);
                oacc = fmaf(v, cZ[d] * (1.0f/1021.0f), oacc);
            }
        }
        // red hazard: next write to red happens only after S1+S2 of next net,
        // which warp0 must also pass after finishing its read above.
    }

    if (warp == 0 && lane < CV)
        atomicAdd(&out[b*CV + lane], oacc);
}

extern "C" void kernel_launch(void* const* d_in, const int* in_sizes, int n_in,
                              void* d_out, int out_size) {
    const int*   ids  = (const int*)  d_in[0];
    const float* mask = (const float*)d_in[1];
    const float* z    = (const float*)d_in[2];
    const float* emb  = (const float*)d_in[3];
    const float* W1   = (const float*)d_in[4];
    const float* b1   = (const float*)d_in[5];
    const float* W2   = (const float*)d_in[6];
    const float* b2   = (const float*)d_in[7];
    const float* W3   = (const float*)d_in[8];
    const float* b3   = (const float*)d_in[9];
    const float* Wh   = (const float*)d_in[10];
    const float* bh   = (const float*)d_in[11];
    float* out = (float*)d_out;

    // repack conv weights into pair-major layout, then stage into constant mem
    repack_kernel<<<(DZV*192 + 255)/256, 256>>>(W1, W2, W3);
    float* scratch = nullptr;
    cudaGetSymbolAddress((void**)&scratch, g_wscratch);
    cudaMemcpyToSymbolAsync(cW1p, scratch,        DZV*96*sizeof(float),  0, cudaMemcpyDeviceToDevice, 0);
    cudaMemcpyToSymbolAsync(cW2p, scratch + 2880, DZV*96*sizeof(float),  0, cudaMemcpyDeviceToDevice, 0);
    cudaMemcpyToSymbolAsync(cW3p, scratch + 5760, DZV*192*sizeof(float), 0, cudaMemcpyDeviceToDevice, 0);
    cudaMemcpyToSymbolAsync(cB1, b1, DZV*4*sizeof(float),  0, cudaMemcpyDeviceToDevice, 0);
    cudaMemcpyToSymbolAsync(cB2, b2, DZV*8*sizeof(float),  0, cudaMemcpyDeviceToDevice, 0);
    cudaMemcpyToSymbolAsync(cB3, b3, DZV*8*sizeof(float),  0, cudaMemcpyDeviceToDevice, 0);
    cudaMemcpyToSymbolAsync(cWh, Wh, DZV*80*sizeof(float), 0, cudaMemcpyDeviceToDevice, 0);
    cudaMemcpyToSymbolAsync(cZ,  z,  DZV*sizeof(float),    0, cudaMemcpyDeviceToDevice, 0);

    init_out_kernel<<<(B_TOT*CV + 255)/256, 256>>>(z, bh, out);

    cudaFuncSetAttribute(ensemble_kernel,
                         cudaFuncAttributeMaxDynamicSharedMemorySize,
                         SMEM_FLOATS * (int)sizeof(float));
    ensemble_kernel<<<dim3(B_TOT, 2, 2), NT, SMEM_FLOATS * (int)sizeof(float)>>>(ids, mask, emb, out);
}